// round 1
// baseline (speedup 1.0000x reference)
#include <cuda_runtime.h>

// Problem constants
#define BB 8
#define NN 1024
#define CC 768
#define HH 12
#define DD 64
#define ROWS (BB * NN)          // 8192
#define QKVC (3 * CC)           // 2304

// Scratch (allocation-free rule: __device__ globals)
__device__ float g_qkv[ROWS * QKVC];                 // 75.5 MB
__device__ float g_heads[ROWS * CC];                 // 25 MB  ([b,n,h,d] flattened)
__device__ float g_attn_fb[BB * HH * NN * NN];       // 402 MB fallback if attn not in d_out

// ---------------------------------------------------------------------------
// GEMM (NT): C[M,N] = A[M,K] * B[N,K]^T + bias[N]
// 128x128 block tile, BK=8, 256 threads, 8x8 per-thread register tile.
// Requires M%128==0, N%128==0, K%8==0 (true for all uses here).
// ---------------------------------------------------------------------------
__global__ __launch_bounds__(256) void gemm_nt_bias(
    const float* __restrict__ A, const float* __restrict__ Bm,
    const float* __restrict__ bias, float* __restrict__ C,
    int M, int N, int K)
{
    __shared__ __align__(16) float As[8][132];
    __shared__ __align__(16) float Bs[8][132];

    const int tid = threadIdx.x;
    const int tx = tid & 15;          // 16 cols of 8
    const int ty = tid >> 4;          // 16 rows of 8
    const int m0 = blockIdx.y * 128;
    const int n0 = blockIdx.x * 128;
    const int lr = tid >> 1;          // 0..127
    const int lk = (tid & 1) * 4;     // 0 or 4

    float acc[8][8];
#pragma unroll
    for (int i = 0; i < 8; i++)
#pragma unroll
        for (int j = 0; j < 8; j++) acc[i][j] = 0.f;

    const float* Ap = A + (size_t)(m0 + lr) * K + lk;
    const float* Bp = Bm + (size_t)(n0 + lr) * K + lk;

    for (int k0 = 0; k0 < K; k0 += 8) {
        float4 av = *(const float4*)(Ap + k0);
        float4 bv = *(const float4*)(Bp + k0);
        As[lk + 0][lr] = av.x; As[lk + 1][lr] = av.y;
        As[lk + 2][lr] = av.z; As[lk + 3][lr] = av.w;
        Bs[lk + 0][lr] = bv.x; Bs[lk + 1][lr] = bv.y;
        Bs[lk + 2][lr] = bv.z; Bs[lk + 3][lr] = bv.w;
        __syncthreads();

#pragma unroll
        for (int kk = 0; kk < 8; kk++) {
            float4 a0 = *(const float4*)&As[kk][ty * 8];
            float4 a1 = *(const float4*)&As[kk][ty * 8 + 4];
            float4 b0 = *(const float4*)&Bs[kk][tx * 8];
            float4 b1 = *(const float4*)&Bs[kk][tx * 8 + 4];
            float a[8] = {a0.x, a0.y, a0.z, a0.w, a1.x, a1.y, a1.z, a1.w};
            float b[8] = {b0.x, b0.y, b0.z, b0.w, b1.x, b1.y, b1.z, b1.w};
#pragma unroll
            for (int i = 0; i < 8; i++)
#pragma unroll
                for (int j = 0; j < 8; j++)
                    acc[i][j] += a[i] * b[j];
        }
        __syncthreads();
    }

    float4 bb0 = *(const float4*)&bias[n0 + tx * 8];
    float4 bb1 = *(const float4*)&bias[n0 + tx * 8 + 4];
#pragma unroll
    for (int i = 0; i < 8; i++) {
        size_t row = (size_t)(m0 + ty * 8 + i);
        float4 o0 = make_float4(acc[i][0] + bb0.x, acc[i][1] + bb0.y,
                                acc[i][2] + bb0.z, acc[i][3] + bb0.w);
        float4 o1 = make_float4(acc[i][4] + bb1.x, acc[i][5] + bb1.y,
                                acc[i][6] + bb1.z, acc[i][7] + bb1.w);
        *(float4*)&C[row * N + n0 + tx * 8] = o0;
        *(float4*)&C[row * N + n0 + tx * 8 + 4] = o1;
    }
}

// ---------------------------------------------------------------------------
// LayerNorm over head_dim=64 for q (part 0, also *SCALE) and k (part 1),
// in place in g_qkv. One warp per (row, part, head).
// ---------------------------------------------------------------------------
__global__ __launch_bounds__(256) void ln_qk(
    float* __restrict__ qkv,
    const float* __restrict__ qg, const float* __restrict__ qb,
    const float* __restrict__ kg, const float* __restrict__ kb)
{
    int wid = (blockIdx.x * blockDim.x + threadIdx.x) >> 5;
    int lane = threadIdx.x & 31;
    // wid in [0, ROWS*24)
    int ph = wid % 24;
    int row = wid / 24;
    int part = ph / HH;
    int h = ph % HH;

    float* p = qkv + (size_t)row * QKVC + part * CC + h * DD;
    float x0 = p[lane];
    float x1 = p[lane + 32];
    float s = x0 + x1;
    float s2 = x0 * x0 + x1 * x1;
#pragma unroll
    for (int o = 16; o; o >>= 1) {
        s += __shfl_xor_sync(0xffffffffu, s, o);
        s2 += __shfl_xor_sync(0xffffffffu, s2, o);
    }
    float mu = s * (1.f / 64.f);
    float var = s2 * (1.f / 64.f) - mu * mu;
    float inv = rsqrtf(var + 1e-5f);
    const float* g = part ? kg : qg;
    const float* be = part ? kb : qb;
    float scale = part ? 1.0f : 0.125f;   // SCALE = 64^-0.5
    p[lane]      = ((x0 - mu) * inv * g[lane]      + be[lane])      * scale;
    p[lane + 32] = ((x1 - mu) * inv * g[lane + 32] + be[lane + 32]) * scale;
}

// ---------------------------------------------------------------------------
// Fused attention: one block per (b,h, 32-query tile).
// Scores S[32][1024] in smem -> softmax -> write attn to gmem -> PV in smem.
// Dynamic smem: S (128KB) + q_s[64][36] + kv[64][68] = 157,696 B.
// ---------------------------------------------------------------------------
#define SMEM_ATTN ((32 * 1024 + 64 * 36 + 64 * 68) * 4)

__global__ __launch_bounds__(256) void attn_kernel(
    const float* __restrict__ qkv, float* __restrict__ attn_out,
    float* __restrict__ heads)
{
    extern __shared__ float sm[];
    float* S   = sm;               // [32][1024]
    float* q_s = sm + 32 * 1024;   // [d=64][qi=32] padded to 36
    float* kv  = q_s + 64 * 36;    // [64][64] padded to 68
    const int QS = 36, KS = 68;

    const int tid = threadIdx.x;
    const int tx = tid & 15;       // 16 cols of 4
    const int ty = tid >> 4;       // 16 rows of 2
    const int qt = blockIdx.x;     // 0..31
    const int bh = blockIdx.y;     // 0..95
    const int b = bh / HH, h = bh % HH;
    const int n0 = qt * 32;
    const size_t base = (size_t)b * NN;

    // Load q tile transposed: q_s[d][qi]
    for (int i = tid; i < 32 * 16; i += 256) {
        int qi = i >> 4, dq = (i & 15) << 2;
        float4 v = *(const float4*)(qkv + (base + n0 + qi) * QKVC + h * DD + dq);
        q_s[(dq + 0) * QS + qi] = v.x; q_s[(dq + 1) * QS + qi] = v.y;
        q_s[(dq + 2) * QS + qi] = v.z; q_s[(dq + 3) * QS + qi] = v.w;
    }

    // ---- Scores: S = q_ln * k_ln^T ----
    for (int kt = 0; kt < 16; kt++) {
        for (int i = tid; i < 64 * 16; i += 256) {
            int kj = i >> 4, dq = (i & 15) << 2;
            float4 v = *(const float4*)(qkv + (base + kt * 64 + kj) * QKVC + CC + h * DD + dq);
            kv[(dq + 0) * KS + kj] = v.x; kv[(dq + 1) * KS + kj] = v.y;
            kv[(dq + 2) * KS + kj] = v.z; kv[(dq + 3) * KS + kj] = v.w;
        }
        __syncthreads();

        float acc[2][4] = {{0.f, 0.f, 0.f, 0.f}, {0.f, 0.f, 0.f, 0.f}};
#pragma unroll 8
        for (int d = 0; d < 64; d++) {
            float a0 = q_s[d * QS + ty * 2];
            float a1 = q_s[d * QS + ty * 2 + 1];
            float4 bv = *(const float4*)&kv[d * KS + tx * 4];
            acc[0][0] += a0 * bv.x; acc[0][1] += a0 * bv.y;
            acc[0][2] += a0 * bv.z; acc[0][3] += a0 * bv.w;
            acc[1][0] += a1 * bv.x; acc[1][1] += a1 * bv.y;
            acc[1][2] += a1 * bv.z; acc[1][3] += a1 * bv.w;
        }
        int c0 = kt * 64 + tx * 4;
#pragma unroll
        for (int i = 0; i < 2; i++) {
            float* Sp = &S[(ty * 2 + i) * 1024 + c0];
            Sp[0] = acc[i][0]; Sp[1] = acc[i][1];
            Sp[2] = acc[i][2]; Sp[3] = acc[i][3];
        }
        __syncthreads();
    }

    // ---- Softmax per row + write attn to gmem ----
    const int warp = tid >> 5, lane = tid & 31;
#pragma unroll
    for (int r = warp * 4; r < warp * 4 + 4; r++) {
        float* Sr = S + r * 1024;
        float m = -1e30f;
#pragma unroll
        for (int it = 0; it < 8; it++) {
            float4 v = *(const float4*)&Sr[it * 128 + lane * 4];
            m = fmaxf(m, fmaxf(fmaxf(v.x, v.y), fmaxf(v.z, v.w)));
        }
#pragma unroll
        for (int o = 16; o; o >>= 1) m = fmaxf(m, __shfl_xor_sync(0xffffffffu, m, o));
        float sum = 0.f;
#pragma unroll
        for (int it = 0; it < 8; it++) {
            float4 v = *(float4*)&Sr[it * 128 + lane * 4];
            v.x = __expf(v.x - m); v.y = __expf(v.y - m);
            v.z = __expf(v.z - m); v.w = __expf(v.w - m);
            *(float4*)&Sr[it * 128 + lane * 4] = v;
            sum += v.x + v.y + v.z + v.w;
        }
#pragma unroll
        for (int o = 16; o; o >>= 1) sum += __shfl_xor_sync(0xffffffffu, sum, o);
        float inv = 1.f / sum;
        float* arow = attn_out + ((size_t)bh * NN + n0 + r) * NN;
#pragma unroll
        for (int it = 0; it < 8; it++) {
            float4 v = *(float4*)&Sr[it * 128 + lane * 4];
            v.x *= inv; v.y *= inv; v.z *= inv; v.w *= inv;
            *(float4*)&Sr[it * 128 + lane * 4] = v;
            *(float4*)&arow[it * 128 + lane * 4] = v;
        }
    }
    __syncthreads();

    // ---- PV: O = P @ V ----
    float o[2][4] = {{0.f, 0.f, 0.f, 0.f}, {0.f, 0.f, 0.f, 0.f}};
    for (int kt = 0; kt < 16; kt++) {
        __syncthreads();
        for (int i = tid; i < 64 * 16; i += 256) {
            int kk = i >> 4, dq = (i & 15) << 2;
            *(float4*)&kv[kk * KS + dq] =
                *(const float4*)(qkv + (base + kt * 64 + kk) * QKVC + 2 * CC + h * DD + dq);
        }
        __syncthreads();
#pragma unroll 8
        for (int kk = 0; kk < 64; kk++) {
            float p0 = S[(ty * 2) * 1024 + kt * 64 + kk];
            float p1 = S[(ty * 2 + 1) * 1024 + kt * 64 + kk];
            float4 vv = *(const float4*)&kv[kk * KS + tx * 4];
            o[0][0] += p0 * vv.x; o[0][1] += p0 * vv.y;
            o[0][2] += p0 * vv.z; o[0][3] += p0 * vv.w;
            o[1][0] += p1 * vv.x; o[1][1] += p1 * vv.y;
            o[1][2] += p1 * vv.z; o[1][3] += p1 * vv.w;
        }
    }
#pragma unroll
    for (int i = 0; i < 2; i++) {
        float4 w = make_float4(o[i][0], o[i][1], o[i][2], o[i][3]);
        *(float4*)&heads[(base + n0 + ty * 2 + i) * CC + h * DD + tx * 4] = w;
    }
}

// ---------------------------------------------------------------------------
// Launch: qkv GEMM -> LN(q,k) -> fused attention (+attn write) -> proj GEMM
// ---------------------------------------------------------------------------
extern "C" void kernel_launch(void* const* d_in, const int* in_sizes, int n_in,
                              void* d_out, int out_size)
{
    const float* x      = (const float*)d_in[0];
    const float* qkv_w  = (const float*)d_in[1];
    const float* qkv_b  = (const float*)d_in[2];
    const float* qg     = (const float*)d_in[3];
    const float* qbeta  = (const float*)d_in[4];
    const float* kg     = (const float*)d_in[5];
    const float* kbeta  = (const float*)d_in[6];
    const float* proj_w = (const float*)d_in[7];
    const float* proj_b = (const float*)d_in[8];
    float* out = (float*)d_out;

    float *qkv_ptr, *heads_ptr, *attn_fb;
    cudaGetSymbolAddress((void**)&qkv_ptr, g_qkv);
    cudaGetSymbolAddress((void**)&heads_ptr, g_heads);
    cudaGetSymbolAddress((void**)&attn_fb, g_attn_fb);

    const long OUT_E  = (long)ROWS * CC;                 // 6,291,456
    const long ATTN_E = (long)BB * HH * NN * NN;         // 100,663,296
    float* attn_ptr = ((long)out_size >= OUT_E + ATTN_E) ? (out + OUT_E) : attn_fb;

    cudaFuncSetAttribute(attn_kernel, cudaFuncAttributeMaxDynamicSharedMemorySize, SMEM_ATTN);

    // 1. qkv = x @ qkv_w^T + qkv_b        [8192, 2304]
    gemm_nt_bias<<<dim3(QKVC / 128, ROWS / 128), 256>>>(x, qkv_w, qkv_b, qkv_ptr,
                                                        ROWS, QKVC, CC);
    // 2. LayerNorm q (with *SCALE) and k, in place
    ln_qk<<<(ROWS * 24) / 8, 256>>>(qkv_ptr, qg, qbeta, kg, kbeta);
    // 3. attn = softmax(q k^T) (written to gmem), heads = attn @ v
    attn_kernel<<<dim3(32, BB * HH), 256, SMEM_ATTN>>>(qkv_ptr, attn_ptr, heads_ptr);
    // 4. out = heads @ proj_w^T + proj_b  [8192, 768]
    gemm_nt_bias<<<dim3(CC / 128, ROWS / 128), 256>>>(heads_ptr, proj_w, proj_b, out,
                                                      ROWS, CC, CC);
}

// round 3
// speedup vs baseline: 1.0097x; 1.0097x over previous
#include <cuda_runtime.h>
#include <cstdint>

// Problem constants
#define BB 8
#define NN 1024
#define CC 768
#define HH 12
#define DD 64
#define ROWS (BB * NN)          // 8192
#define QKVC (3 * CC)           // 2304

// Scratch (allocation-free rule: __device__ globals)
__device__ float g_qkv[ROWS * QKVC];                 // 75.5 MB
__device__ float g_heads[ROWS * CC];                 // 25 MB  ([b,n,h,d] flattened)
__device__ float g_attn_fb[BB * HH * NN * NN];       // 402 MB fallback if attn not in d_out

// ---------------------------------------------------------------------------
// TF32 helpers (3xTF32 split-precision GEMM on the tensor pipe)
// ---------------------------------------------------------------------------
__device__ __forceinline__ uint32_t f2tf(float x) {
    uint32_t r;
    asm("cvt.rna.tf32.f32 %0, %1;" : "=r"(r) : "f"(x));
    return r;
}

__device__ __forceinline__ void mma8(float (&c)[4], const uint32_t (&a)[4],
                                     const uint32_t (&b)[2]) {
    asm volatile(
        "mma.sync.aligned.m16n8k8.row.col.f32.tf32.tf32.f32 "
        "{%0,%1,%2,%3},{%4,%5,%6,%7},{%8,%9},{%0,%1,%2,%3};"
        : "+f"(c[0]), "+f"(c[1]), "+f"(c[2]), "+f"(c[3])
        : "r"(a[0]), "r"(a[1]), "r"(a[2]), "r"(a[3]), "r"(b[0]), "r"(b[1]));
}

// ---------------------------------------------------------------------------
// TF32 tensor-core GEMM (NT): C[M,N] = A[M,K] * B[N,K]^T + bias[N]
// 128x128 block tile, BK=16, 256 threads (8 warps, 2x4 -> 64x32 warp tiles).
// 3xTF32: hi/lo split stored in smem; hi*hi + hi*lo + lo*hi per mma tile.
// Requires M%128==0, N%128==0, K%16==0 (true for all uses here).
// ---------------------------------------------------------------------------
#define BKK 16
#define PAD 136   // (8*k + m) % 32 distinct per warp quad -> conflict-free frag LDS

__device__ __forceinline__ void split_store(uint32_t (*s)[BKK][PAD], int k, int r,
                                            float4 v) {
    float xs[4] = {v.x, v.y, v.z, v.w};
#pragma unroll
    for (int j = 0; j < 4; j++) {
        uint32_t hi = f2tf(xs[j]);
        s[0][k + j][r] = hi;
        s[1][k + j][r] = f2tf(xs[j] - __uint_as_float(hi));
    }
}

__global__ __launch_bounds__(256) void gemm_tf32_nt(
    const float* __restrict__ A, const float* __restrict__ Bm,
    const float* __restrict__ bias, float* __restrict__ C,
    int M, int N, int K)
{
    __shared__ __align__(16) uint32_t As[2][BKK][PAD];   // [hi/lo][k][m]
    __shared__ __align__(16) uint32_t Bs[2][BKK][PAD];   // [hi/lo][k][n]

    const int tid = threadIdx.x;
    const int m0 = blockIdx.y * 128;
    const int n0 = blockIdx.x * 128;
    const int lane = tid & 31, warp = tid >> 5;
    const int gid = lane >> 2, tig = lane & 3;
    const int wm = (warp >> 2) * 64;    // warp m offset (2 rows of warps)
    const int wn = (warp & 3) * 32;     // warp n offset (4 cols of warps)

    // Loader: each thread loads rows lrow and lrow+64, 4 consecutive k (lkq).
    const int lrow = tid >> 2;
    const int lkq = (tid & 3) * 4;
    const float* Ap = A + (size_t)(m0 + lrow) * K + lkq;
    const float* Bp = Bm + (size_t)(n0 + lrow) * K + lkq;
    const size_t rstep = (size_t)64 * K;

    float c[4][4][4];
#pragma unroll
    for (int i = 0; i < 4; i++)
#pragma unroll
        for (int j = 0; j < 4; j++)
#pragma unroll
            for (int q = 0; q < 4; q++) c[i][j][q] = 0.f;

    // Prefetch tile 0
    float4 pa0 = *(const float4*)(Ap);
    float4 pa1 = *(const float4*)(Ap + rstep);
    float4 pb0 = *(const float4*)(Bp);
    float4 pb1 = *(const float4*)(Bp + rstep);

    const int nkt = K / BKK;
    for (int kt = 0; kt < nkt; kt++) {
        split_store(As, lkq, lrow, pa0);
        split_store(As, lkq, lrow + 64, pa1);
        split_store(Bs, lkq, lrow, pb0);
        split_store(Bs, lkq, lrow + 64, pb1);
        __syncthreads();

        if (kt + 1 < nkt) {   // issue next tile's LDGs early; latency hides under MMAs
            const float* Ap2 = Ap + (size_t)(kt + 1) * BKK;
            const float* Bp2 = Bp + (size_t)(kt + 1) * BKK;
            pa0 = *(const float4*)(Ap2);
            pa1 = *(const float4*)(Ap2 + rstep);
            pb0 = *(const float4*)(Bp2);
            pb1 = *(const float4*)(Bp2 + rstep);
        }

#pragma unroll
        for (int s = 0; s < 2; s++) {
            const int k0 = s * 8 + tig, k1 = k0 + 4;
            uint32_t ah[4][4], al[4][4], bh[4][2], bl[4][2];
#pragma unroll
            for (int mi = 0; mi < 4; mi++) {
                int ra = wm + mi * 16 + gid;
                ah[mi][0] = As[0][k0][ra];     ah[mi][1] = As[0][k0][ra + 8];
                ah[mi][2] = As[0][k1][ra];     ah[mi][3] = As[0][k1][ra + 8];
                al[mi][0] = As[1][k0][ra];     al[mi][1] = As[1][k0][ra + 8];
                al[mi][2] = As[1][k1][ra];     al[mi][3] = As[1][k1][ra + 8];
            }
#pragma unroll
            for (int ni = 0; ni < 4; ni++) {
                int rb = wn + ni * 8 + gid;
                bh[ni][0] = Bs[0][k0][rb];     bh[ni][1] = Bs[0][k1][rb];
                bl[ni][0] = Bs[1][k0][rb];     bl[ni][1] = Bs[1][k1][rb];
            }
#pragma unroll
            for (int mi = 0; mi < 4; mi++)
#pragma unroll
                for (int ni = 0; ni < 4; ni++) {
                    mma8(c[mi][ni], ah[mi], bl[ni]);  // hi*lo
                    mma8(c[mi][ni], al[mi], bh[ni]);  // lo*hi
                    mma8(c[mi][ni], ah[mi], bh[ni]);  // hi*hi
                }
        }
        __syncthreads();
    }

    // Epilogue: c frag (gid rows, 2*tig cols) + bias, float2 stores
#pragma unroll
    for (int mi = 0; mi < 4; mi++) {
        int row0 = m0 + wm + mi * 16 + gid;
#pragma unroll
        for (int ni = 0; ni < 4; ni++) {
            int col = n0 + wn + ni * 8 + tig * 2;
            float2 bb = *(const float2*)&bias[col];
            float2 o0 = make_float2(c[mi][ni][0] + bb.x, c[mi][ni][1] + bb.y);
            float2 o1 = make_float2(c[mi][ni][2] + bb.x, c[mi][ni][3] + bb.y);
            *(float2*)&C[(size_t)row0 * N + col] = o0;
            *(float2*)&C[(size_t)(row0 + 8) * N + col] = o1;
        }
    }
}

// ---------------------------------------------------------------------------
// LayerNorm over head_dim=64 for q (part 0, also *SCALE) and k (part 1),
// in place in g_qkv. One warp per (row, part, head).
// ---------------------------------------------------------------------------
__global__ __launch_bounds__(256) void ln_qk(
    float* __restrict__ qkv,
    const float* __restrict__ qg, const float* __restrict__ qb,
    const float* __restrict__ kg, const float* __restrict__ kb)
{
    int wid = (blockIdx.x * blockDim.x + threadIdx.x) >> 5;
    int lane = threadIdx.x & 31;
    int ph = wid % 24;
    int row = wid / 24;
    int part = ph / HH;
    int h = ph % HH;

    float* p = qkv + (size_t)row * QKVC + part * CC + h * DD;
    float x0 = p[lane];
    float x1 = p[lane + 32];
    float s = x0 + x1;
    float s2 = x0 * x0 + x1 * x1;
#pragma unroll
    for (int o = 16; o; o >>= 1) {
        s += __shfl_xor_sync(0xffffffffu, s, o);
        s2 += __shfl_xor_sync(0xffffffffu, s2, o);
    }
    float mu = s * (1.f / 64.f);
    float var = s2 * (1.f / 64.f) - mu * mu;
    float inv = rsqrtf(var + 1e-5f);
    const float* g = part ? kg : qg;
    const float* be = part ? kb : qb;
    float scale = part ? 1.0f : 0.125f;   // SCALE = 64^-0.5
    p[lane]      = ((x0 - mu) * inv * g[lane]      + be[lane])      * scale;
    p[lane + 32] = ((x1 - mu) * inv * g[lane + 32] + be[lane + 32]) * scale;
}

// ---------------------------------------------------------------------------
// Fused attention: one block per (b,h, 32-query tile).
// Scores S[32][1024] in smem -> softmax -> write attn to gmem -> PV in smem.
// Dynamic smem: S (128KB) + q_s[64][36] + kv[64][68] = 157,696 B.
// ---------------------------------------------------------------------------
#define SMEM_ATTN ((32 * 1024 + 64 * 36 + 64 * 68) * 4)

__global__ __launch_bounds__(256) void attn_kernel(
    const float* __restrict__ qkv, float* __restrict__ attn_out,
    float* __restrict__ heads)
{
    extern __shared__ float sm[];
    float* S   = sm;               // [32][1024]
    float* q_s = sm + 32 * 1024;   // [d=64][qi=32] padded to 36
    float* kv  = q_s + 64 * 36;    // [64][64] padded to 68
    const int QS = 36, KS = 68;

    const int tid = threadIdx.x;
    const int tx = tid & 15;       // 16 cols of 4
    const int ty = tid >> 4;       // 16 rows of 2
    const int qt = blockIdx.x;     // 0..31
    const int bh = blockIdx.y;     // 0..95
    const int b = bh / HH, h = bh % HH;
    const int n0 = qt * 32;
    const size_t base = (size_t)b * NN;

    // Load q tile transposed: q_s[d][qi]
    for (int i = tid; i < 32 * 16; i += 256) {
        int qi = i >> 4, dq = (i & 15) << 2;
        float4 v = *(const float4*)(qkv + (base + n0 + qi) * QKVC + h * DD + dq);
        q_s[(dq + 0) * QS + qi] = v.x; q_s[(dq + 1) * QS + qi] = v.y;
        q_s[(dq + 2) * QS + qi] = v.z; q_s[(dq + 3) * QS + qi] = v.w;
    }

    // ---- Scores: S = q_ln * k_ln^T ----
    for (int kt = 0; kt < 16; kt++) {
        for (int i = tid; i < 64 * 16; i += 256) {
            int kj = i >> 4, dq = (i & 15) << 2;
            float4 v = *(const float4*)(qkv + (base + kt * 64 + kj) * QKVC + CC + h * DD + dq);
            kv[(dq + 0) * KS + kj] = v.x; kv[(dq + 1) * KS + kj] = v.y;
            kv[(dq + 2) * KS + kj] = v.z; kv[(dq + 3) * KS + kj] = v.w;
        }
        __syncthreads();

        float acc[2][4] = {{0.f, 0.f, 0.f, 0.f}, {0.f, 0.f, 0.f, 0.f}};
#pragma unroll 8
        for (int d = 0; d < 64; d++) {
            float a0 = q_s[d * QS + ty * 2];
            float a1 = q_s[d * QS + ty * 2 + 1];
            float4 bv = *(const float4*)&kv[d * KS + tx * 4];
            acc[0][0] += a0 * bv.x; acc[0][1] += a0 * bv.y;
            acc[0][2] += a0 * bv.z; acc[0][3] += a0 * bv.w;
            acc[1][0] += a1 * bv.x; acc[1][1] += a1 * bv.y;
            acc[1][2] += a1 * bv.z; acc[1][3] += a1 * bv.w;
        }
        int c0 = kt * 64 + tx * 4;
#pragma unroll
        for (int i = 0; i < 2; i++) {
            float* Sp = &S[(ty * 2 + i) * 1024 + c0];
            Sp[0] = acc[i][0]; Sp[1] = acc[i][1];
            Sp[2] = acc[i][2]; Sp[3] = acc[i][3];
        }
        __syncthreads();
    }

    // ---- Softmax per row + write attn to gmem ----
    const int warp = tid >> 5, lane = tid & 31;
#pragma unroll
    for (int r = warp * 4; r < warp * 4 + 4; r++) {
        float* Sr = S + r * 1024;
        float m = -1e30f;
#pragma unroll
        for (int it = 0; it < 8; it++) {
            float4 v = *(const float4*)&Sr[it * 128 + lane * 4];
            m = fmaxf(m, fmaxf(fmaxf(v.x, v.y), fmaxf(v.z, v.w)));
        }
#pragma unroll
        for (int o = 16; o; o >>= 1) m = fmaxf(m, __shfl_xor_sync(0xffffffffu, m, o));
        float sum = 0.f;
#pragma unroll
        for (int it = 0; it < 8; it++) {
            float4 v = *(float4*)&Sr[it * 128 + lane * 4];
            v.x = __expf(v.x - m); v.y = __expf(v.y - m);
            v.z = __expf(v.z - m); v.w = __expf(v.w - m);
            *(float4*)&Sr[it * 128 + lane * 4] = v;
            sum += v.x + v.y + v.z + v.w;
        }
#pragma unroll
        for (int o = 16; o; o >>= 1) sum += __shfl_xor_sync(0xffffffffu, sum, o);
        float inv = 1.f / sum;
        float* arow = attn_out + ((size_t)bh * NN + n0 + r) * NN;
#pragma unroll
        for (int it = 0; it < 8; it++) {
            float4 v = *(float4*)&Sr[it * 128 + lane * 4];
            v.x *= inv; v.y *= inv; v.z *= inv; v.w *= inv;
            *(float4*)&Sr[it * 128 + lane * 4] = v;
            *(float4*)&arow[it * 128 + lane * 4] = v;
        }
    }
    __syncthreads();

    // ---- PV: O = P @ V ----
    float o[2][4] = {{0.f, 0.f, 0.f, 0.f}, {0.f, 0.f, 0.f, 0.f}};
    for (int kt = 0; kt < 16; kt++) {
        __syncthreads();
        for (int i = tid; i < 64 * 16; i += 256) {
            int kk = i >> 4, dq = (i & 15) << 2;
            *(float4*)&kv[kk * KS + dq] =
                *(const float4*)(qkv + (base + kt * 64 + kk) * QKVC + 2 * CC + h * DD + dq);
        }
        __syncthreads();
#pragma unroll 8
        for (int kk = 0; kk < 64; kk++) {
            float p0 = S[(ty * 2) * 1024 + kt * 64 + kk];
            float p1 = S[(ty * 2 + 1) * 1024 + kt * 64 + kk];
            float4 vv = *(const float4*)&kv[kk * KS + tx * 4];
            o[0][0] += p0 * vv.x; o[0][1] += p0 * vv.y;
            o[0][2] += p0 * vv.z; o[0][3] += p0 * vv.w;
            o[1][0] += p1 * vv.x; o[1][1] += p1 * vv.y;
            o[1][2] += p1 * vv.z; o[1][3] += p1 * vv.w;
        }
    }
#pragma unroll
    for (int i = 0; i < 2; i++) {
        float4 w = make_float4(o[i][0], o[i][1], o[i][2], o[i][3]);
        *(float4*)&heads[(base + n0 + ty * 2 + i) * CC + h * DD + tx * 4] = w;
    }
}

// ---------------------------------------------------------------------------
// Launch: qkv GEMM (tf32 3x) -> LN(q,k) -> fused attention -> proj GEMM (tf32 3x)
// ---------------------------------------------------------------------------
extern "C" void kernel_launch(void* const* d_in, const int* in_sizes, int n_in,
                              void* d_out, int out_size)
{
    const float* x      = (const float*)d_in[0];
    const float* qkv_w  = (const float*)d_in[1];
    const float* qkv_b  = (const float*)d_in[2];
    const float* qg     = (const float*)d_in[3];
    const float* qbeta  = (const float*)d_in[4];
    const float* kg     = (const float*)d_in[5];
    const float* kbeta  = (const float*)d_in[6];
    const float* proj_w = (const float*)d_in[7];
    const float* proj_b = (const float*)d_in[8];
    float* out = (float*)d_out;

    float *qkv_ptr, *heads_ptr, *attn_fb;
    cudaGetSymbolAddress((void**)&qkv_ptr, g_qkv);
    cudaGetSymbolAddress((void**)&heads_ptr, g_heads);
    cudaGetSymbolAddress((void**)&attn_fb, g_attn_fb);

    const long OUT_E  = (long)ROWS * CC;                 // 6,291,456
    const long ATTN_E = (long)BB * HH * NN * NN;         // 100,663,296
    float* attn_ptr = ((long)out_size >= OUT_E + ATTN_E) ? (out + OUT_E) : attn_fb;

    cudaFuncSetAttribute(attn_kernel, cudaFuncAttributeMaxDynamicSharedMemorySize, SMEM_ATTN);

    // 1. qkv = x @ qkv_w^T + qkv_b        [8192, 2304]
    gemm_tf32_nt<<<dim3(QKVC / 128, ROWS / 128), 256>>>(x, qkv_w, qkv_b, qkv_ptr,
                                                        ROWS, QKVC, CC);
    // 2. LayerNorm q (with *SCALE) and k, in place
    ln_qk<<<(ROWS * 24) / 8, 256>>>(qkv_ptr, qg, qbeta, kg, kbeta);
    // 3. attn = softmax(q k^T) (written to gmem), heads = attn @ v
    attn_kernel<<<dim3(32, BB * HH), 256, SMEM_ATTN>>>(qkv_ptr, attn_ptr, heads_ptr);
    // 4. out = heads @ proj_w^T + proj_b  [8192, 768]
    gemm_tf32_nt<<<dim3(CC / 128, ROWS / 128), 256>>>(heads_ptr, proj_w, proj_b, out,
                                                      ROWS, CC, CC);
}

// round 6
// speedup vs baseline: 1.0812x; 1.0708x over previous
#include <cuda_runtime.h>
#include <cstdint>

// Problem constants
#define BB 8
#define NN 1024
#define CC 768
#define HH 12
#define DD 64
#define ROWS (BB * NN)          // 8192
#define QKVC (3 * CC)           // 2304

// Scratch (allocation-free rule: __device__ globals)
__device__ float g_qkv[ROWS * QKVC];                 // 75.5 MB
__device__ float g_heads[ROWS * CC];                 // 25 MB  ([b,n,h,d] flattened)
__device__ float g_attn_fb[BB * HH * NN * NN];       // 402 MB fallback if attn not in d_out

// ---------------------------------------------------------------------------
// TF32 helpers (3xTF32 split-precision on the tensor pipe)
// ---------------------------------------------------------------------------
__device__ __forceinline__ uint32_t f2tf(float x) {
    uint32_t r;
    asm("cvt.rna.tf32.f32 %0, %1;" : "=r"(r) : "f"(x));
    return r;
}

__device__ __forceinline__ void mma8(float (&c)[4], const uint32_t (&a)[4],
                                     const uint32_t (&b)[2]) {
    asm volatile(
        "mma.sync.aligned.m16n8k8.row.col.f32.tf32.tf32.f32 "
        "{%0,%1,%2,%3},{%4,%5,%6,%7},{%8,%9},{%0,%1,%2,%3};"
        : "+f"(c[0]), "+f"(c[1]), "+f"(c[2]), "+f"(c[3])
        : "r"(a[0]), "r"(a[1]), "r"(a[2]), "r"(a[3]), "r"(b[0]), "r"(b[1]));
}

// ---------------------------------------------------------------------------
// TF32 tensor-core GEMM (NT): C[M,N] = A[M,K] * B[N,K]^T + bias[N]
// (validated R3: rel_err 7e-6, 269us for the 29-GFLOP QKV GEMM)
// ---------------------------------------------------------------------------
#define BKK 16
#define PAD 136

__device__ __forceinline__ void split_store(uint32_t (*s)[BKK][PAD], int k, int r,
                                            float4 v) {
    float xs[4] = {v.x, v.y, v.z, v.w};
#pragma unroll
    for (int j = 0; j < 4; j++) {
        uint32_t hi = f2tf(xs[j]);
        s[0][k + j][r] = hi;
        s[1][k + j][r] = f2tf(xs[j] - __uint_as_float(hi));
    }
}

__global__ __launch_bounds__(256) void gemm_tf32_nt(
    const float* __restrict__ A, const float* __restrict__ Bm,
    const float* __restrict__ bias, float* __restrict__ C,
    int M, int N, int K)
{
    __shared__ __align__(16) uint32_t As[2][BKK][PAD];
    __shared__ __align__(16) uint32_t Bs[2][BKK][PAD];

    const int tid = threadIdx.x;
    const int m0 = blockIdx.y * 128;
    const int n0 = blockIdx.x * 128;
    const int lane = tid & 31, warp = tid >> 5;
    const int gid = lane >> 2, tig = lane & 3;
    const int wm = (warp >> 2) * 64;
    const int wn = (warp & 3) * 32;

    const int lrow = tid >> 2;
    const int lkq = (tid & 3) * 4;
    const float* Ap = A + (size_t)(m0 + lrow) * K + lkq;
    const float* Bp = Bm + (size_t)(n0 + lrow) * K + lkq;
    const size_t rstep = (size_t)64 * K;

    float c[4][4][4];
#pragma unroll
    for (int i = 0; i < 4; i++)
#pragma unroll
        for (int j = 0; j < 4; j++)
#pragma unroll
            for (int q = 0; q < 4; q++) c[i][j][q] = 0.f;

    float4 pa0 = *(const float4*)(Ap);
    float4 pa1 = *(const float4*)(Ap + rstep);
    float4 pb0 = *(const float4*)(Bp);
    float4 pb1 = *(const float4*)(Bp + rstep);

    const int nkt = K / BKK;
    for (int kt = 0; kt < nkt; kt++) {
        split_store(As, lkq, lrow, pa0);
        split_store(As, lkq, lrow + 64, pa1);
        split_store(Bs, lkq, lrow, pb0);
        split_store(Bs, lkq, lrow + 64, pb1);
        __syncthreads();

        if (kt + 1 < nkt) {
            const float* Ap2 = Ap + (size_t)(kt + 1) * BKK;
            const float* Bp2 = Bp + (size_t)(kt + 1) * BKK;
            pa0 = *(const float4*)(Ap2);
            pa1 = *(const float4*)(Ap2 + rstep);
            pb0 = *(const float4*)(Bp2);
            pb1 = *(const float4*)(Bp2 + rstep);
        }

#pragma unroll
        for (int s = 0; s < 2; s++) {
            const int k0 = s * 8 + tig, k1 = k0 + 4;
            uint32_t ah[4][4], al[4][4], bh[4][2], bl[4][2];
#pragma unroll
            for (int mi = 0; mi < 4; mi++) {
                int ra = wm + mi * 16 + gid;
                ah[mi][0] = As[0][k0][ra];     ah[mi][1] = As[0][k0][ra + 8];
                ah[mi][2] = As[0][k1][ra];     ah[mi][3] = As[0][k1][ra + 8];
                al[mi][0] = As[1][k0][ra];     al[mi][1] = As[1][k0][ra + 8];
                al[mi][2] = As[1][k1][ra];     al[mi][3] = As[1][k1][ra + 8];
            }
#pragma unroll
            for (int ni = 0; ni < 4; ni++) {
                int rb = wn + ni * 8 + gid;
                bh[ni][0] = Bs[0][k0][rb];     bh[ni][1] = Bs[0][k1][rb];
                bl[ni][0] = Bs[1][k0][rb];     bl[ni][1] = Bs[1][k1][rb];
            }
#pragma unroll
            for (int mi = 0; mi < 4; mi++)
#pragma unroll
                for (int ni = 0; ni < 4; ni++) {
                    mma8(c[mi][ni], ah[mi], bl[ni]);
                    mma8(c[mi][ni], al[mi], bh[ni]);
                    mma8(c[mi][ni], ah[mi], bh[ni]);
                }
        }
        __syncthreads();
    }

#pragma unroll
    for (int mi = 0; mi < 4; mi++) {
        int row0 = m0 + wm + mi * 16 + gid;
#pragma unroll
        for (int ni = 0; ni < 4; ni++) {
            int col = n0 + wn + ni * 8 + tig * 2;
            float2 bb = *(const float2*)&bias[col];
            float2 o0 = make_float2(c[mi][ni][0] + bb.x, c[mi][ni][1] + bb.y);
            float2 o1 = make_float2(c[mi][ni][2] + bb.x, c[mi][ni][3] + bb.y);
            *(float2*)&C[(size_t)row0 * N + col] = o0;
            *(float2*)&C[(size_t)(row0 + 8) * N + col] = o1;
        }
    }
}

// ---------------------------------------------------------------------------
// LayerNorm over head_dim=64 for q (part 0, also *SCALE) and k (part 1)
// ---------------------------------------------------------------------------
__global__ __launch_bounds__(256) void ln_qk(
    float* __restrict__ qkv,
    const float* __restrict__ qg, const float* __restrict__ qb,
    const float* __restrict__ kg, const float* __restrict__ kb)
{
    int wid = (blockIdx.x * blockDim.x + threadIdx.x) >> 5;
    int lane = threadIdx.x & 31;
    int ph = wid % 24;
    int row = wid / 24;
    int part = ph / HH;
    int h = ph % HH;

    float* p = qkv + (size_t)row * QKVC + part * CC + h * DD;
    float x0 = p[lane];
    float x1 = p[lane + 32];
    float s = x0 + x1;
    float s2 = x0 * x0 + x1 * x1;
#pragma unroll
    for (int o = 16; o; o >>= 1) {
        s += __shfl_xor_sync(0xffffffffu, s, o);
        s2 += __shfl_xor_sync(0xffffffffu, s2, o);
    }
    float mu = s * (1.f / 64.f);
    float var = s2 * (1.f / 64.f) - mu * mu;
    float inv = rsqrtf(var + 1e-5f);
    const float* g = part ? kg : qg;
    const float* be = part ? kb : qb;
    float scale = part ? 1.0f : 0.125f;   // SCALE = 64^-0.5
    p[lane]      = ((x0 - mu) * inv * g[lane]      + be[lane])      * scale;
    p[lane + 32] = ((x1 - mu) * inv * g[lane + 32] + be[lane + 32]) * scale;
}

// ---------------------------------------------------------------------------
// Tensor-core fused attention. One block per (b,h, 32-query tile).
// Scores via 3xTF32 MMA into S[32][1028] smem -> softmax -> attn write -> PV MMA.
// Smem: S 32*1028 + Qs 2*64*40 + KVs 2*64*136 = 55424 words = 221,696 B.
// Pads: SPAD%32==4 -> PV S-reads conflict-free; QP/KP -> frag LDS bank 8*tig+gid.
// ---------------------------------------------------------------------------
#define SPAD 1028
#define QP 40
#define KP 136
#define SMEM_ATTN ((32 * SPAD + 2 * 64 * QP + 2 * 64 * KP) * 4)

__global__ __launch_bounds__(256) void attn_kernel(
    const float* __restrict__ qkv, float* __restrict__ attn_out,
    float* __restrict__ heads)
{
    extern __shared__ float sm[];
    float* S = sm;                                        // [32][SPAD]
    uint32_t* Qs  = (uint32_t*)(sm + 32 * SPAD);          // [2][64][QP]  ([k][m])
    uint32_t* KVs = Qs + 2 * 64 * QP;                     // [2][64][KP]

    const int tid = threadIdx.x;
    const int lane = tid & 31, warp = tid >> 5;
    const int gid = lane >> 2, tig = lane & 3;
    const int qt = blockIdx.x;     // 0..31
    const int bh = blockIdx.y;     // 0..95
    const int b = bh / HH, h = bh % HH;
    const int n0 = qt * 32;
    const size_t base = (size_t)b * NN;

    // ---- Load Q tile (32x64) -> tf32 hi/lo, transposed [k][m] ----
    for (int i = tid; i < 32 * 16; i += 256) {
        int qi = i >> 4, dq = (i & 15) << 2;
        float4 v = *(const float4*)(qkv + (base + n0 + qi) * QKVC + h * DD + dq);
        float xs[4] = {v.x, v.y, v.z, v.w};
#pragma unroll
        for (int j = 0; j < 4; j++) {
            uint32_t hi = f2tf(xs[j]);
            Qs[(dq + j) * QP + qi] = hi;
            Qs[64 * QP + (dq + j) * QP + qi] = f2tf(xs[j] - __uint_as_float(hi));
        }
    }

    // ---- Scores: S(32x1024) = Q * K^T via 3xTF32 MMA, 8 tiles of 128 keys ----
    const int wm = (warp & 1) * 16;        // 2 m-warps x 4 n-warps
    const int wn = (warp >> 1) * 32;
    for (int kt = 0; kt < 8; kt++) {       // 8 * 128 = 1024 keys (NOT 16!)
        // stage K tile (128 keys x 64) as tf32 hi/lo, [k][n] pad KP
        for (int i = tid; i < 128 * 16; i += 256) {
            int kj = i >> 4, dq = (i & 15) << 2;
            float4 v = *(const float4*)(qkv + (base + kt * 128 + kj) * QKVC + CC + h * DD + dq);
            float xs[4] = {v.x, v.y, v.z, v.w};
#pragma unroll
            for (int j = 0; j < 4; j++) {
                uint32_t hi = f2tf(xs[j]);
                KVs[(dq + j) * KP + kj] = hi;
                KVs[64 * KP + (dq + j) * KP + kj] = f2tf(xs[j] - __uint_as_float(hi));
            }
        }
        __syncthreads();

        float c[4][4];
#pragma unroll
        for (int ni = 0; ni < 4; ni++)
#pragma unroll
            for (int q = 0; q < 4; q++) c[ni][q] = 0.f;

#pragma unroll
        for (int ks = 0; ks < 8; ks++) {
            const int k0 = ks * 8 + tig, k1 = k0 + 4;
            const int ra = wm + gid;
            uint32_t ah[4], al[4];
            ah[0] = Qs[k0 * QP + ra];  ah[1] = Qs[k0 * QP + ra + 8];
            ah[2] = Qs[k1 * QP + ra];  ah[3] = Qs[k1 * QP + ra + 8];
            al[0] = Qs[64 * QP + k0 * QP + ra];  al[1] = Qs[64 * QP + k0 * QP + ra + 8];
            al[2] = Qs[64 * QP + k1 * QP + ra];  al[3] = Qs[64 * QP + k1 * QP + ra + 8];
#pragma unroll
            for (int ni = 0; ni < 4; ni++) {
                int rb = wn + ni * 8 + gid;
                uint32_t bh2[2] = {KVs[k0 * KP + rb], KVs[k1 * KP + rb]};
                uint32_t bl2[2] = {KVs[64 * KP + k0 * KP + rb], KVs[64 * KP + k1 * KP + rb]};
                mma8(c[ni], ah, bl2);
                mma8(c[ni], al, bh2);
                mma8(c[ni], ah, bh2);
            }
        }
        // write S tile
#pragma unroll
        for (int ni = 0; ni < 4; ni++) {
            int col = kt * 128 + wn + ni * 8 + tig * 2;
            *(float2*)&S[(wm + gid) * SPAD + col]     = make_float2(c[ni][0], c[ni][1]);
            *(float2*)&S[(wm + gid + 8) * SPAD + col] = make_float2(c[ni][2], c[ni][3]);
        }
        __syncthreads();
    }

    // ---- Softmax per row + single attn write ----
#pragma unroll
    for (int r = warp * 4; r < warp * 4 + 4; r++) {
        float* Sr = S + r * SPAD;
        float m = -1e30f;
#pragma unroll
        for (int it = 0; it < 8; it++) {
            float4 v = *(const float4*)&Sr[it * 128 + lane * 4];
            m = fmaxf(m, fmaxf(fmaxf(v.x, v.y), fmaxf(v.z, v.w)));
        }
#pragma unroll
        for (int o = 16; o; o >>= 1) m = fmaxf(m, __shfl_xor_sync(0xffffffffu, m, o));
        float sum = 0.f;
#pragma unroll
        for (int it = 0; it < 8; it++) {
            float4 v = *(float4*)&Sr[it * 128 + lane * 4];
            v.x = __expf(v.x - m); v.y = __expf(v.y - m);
            v.z = __expf(v.z - m); v.w = __expf(v.w - m);
            *(float4*)&Sr[it * 128 + lane * 4] = v;
            sum += v.x + v.y + v.z + v.w;
        }
#pragma unroll
        for (int o = 16; o; o >>= 1) sum += __shfl_xor_sync(0xffffffffu, sum, o);
        float inv = 1.f / sum;
        float* arow = attn_out + ((size_t)bh * NN + n0 + r) * NN;
#pragma unroll
        for (int it = 0; it < 8; it++) {
            float4 v = *(float4*)&Sr[it * 128 + lane * 4];
            v.x *= inv; v.y *= inv; v.z *= inv; v.w *= inv;
            *(float4*)&Sr[it * 128 + lane * 4] = v;
            *(float4*)&arow[it * 128 + lane * 4] = v;
        }
    }
    __syncthreads();

    // ---- PV: O(32x64) = P * V via 3xTF32 MMA, 16 tiles of 64 keys ----
    const int wnd = (warp >> 1) * 16;      // 4 n-warps x 16 d-cols, 2 m-warps
    float o[2][4];
#pragma unroll
    for (int ni = 0; ni < 2; ni++)
#pragma unroll
        for (int q = 0; q < 4; q++) o[ni][q] = 0.f;

    for (int kt = 0; kt < 16; kt++) {
        // stage V tile (64 keys x 64 d) as tf32 hi/lo, [key][d] pad KP
        for (int i = tid; i < 64 * 16; i += 256) {
            int kj = i >> 4, dq = (i & 15) << 2;
            float4 v = *(const float4*)(qkv + (base + kt * 64 + kj) * QKVC + 2 * CC + h * DD + dq);
            float xs[4] = {v.x, v.y, v.z, v.w};
#pragma unroll
            for (int j = 0; j < 4; j++) {
                uint32_t hi = f2tf(xs[j]);
                KVs[kj * KP + dq + j] = hi;
                KVs[64 * KP + kj * KP + dq + j] = f2tf(xs[j] - __uint_as_float(hi));
            }
        }
        __syncthreads();

#pragma unroll
        for (int ks = 0; ks < 8; ks++) {
            const int k0 = ks * 8 + tig, k1 = k0 + 4;
            const int ra = wm + gid;
            // P frags from S (fp32) -> hi/lo in registers
            float x0 = S[ra * SPAD + kt * 64 + k0];
            float x1 = S[(ra + 8) * SPAD + kt * 64 + k0];
            float x2 = S[ra * SPAD + kt * 64 + k1];
            float x3 = S[(ra + 8) * SPAD + kt * 64 + k1];
            uint32_t ah[4], al[4];
            ah[0] = f2tf(x0); al[0] = f2tf(x0 - __uint_as_float(ah[0]));
            ah[1] = f2tf(x1); al[1] = f2tf(x1 - __uint_as_float(ah[1]));
            ah[2] = f2tf(x2); al[2] = f2tf(x2 - __uint_as_float(ah[2]));
            ah[3] = f2tf(x3); al[3] = f2tf(x3 - __uint_as_float(ah[3]));
#pragma unroll
            for (int ni = 0; ni < 2; ni++) {
                int rb = wnd + ni * 8 + gid;
                uint32_t bh2[2] = {KVs[k0 * KP + rb], KVs[k1 * KP + rb]};
                uint32_t bl2[2] = {KVs[64 * KP + k0 * KP + rb], KVs[64 * KP + k1 * KP + rb]};
                mma8(o[ni], ah, bl2);
                mma8(o[ni], al, bh2);
                mma8(o[ni], ah, bh2);
            }
        }
        __syncthreads();
    }

    // write heads [row][h*64+d]
#pragma unroll
    for (int ni = 0; ni < 2; ni++) {
        int col = h * DD + wnd + ni * 8 + tig * 2;
        *(float2*)&heads[(base + n0 + wm + gid) * CC + col] =
            make_float2(o[ni][0], o[ni][1]);
        *(float2*)&heads[(base + n0 + wm + gid + 8) * CC + col] =
            make_float2(o[ni][2], o[ni][3]);
    }
}

// ---------------------------------------------------------------------------
// Launch: qkv GEMM (tf32) -> LN(q,k) -> tensor attention -> proj GEMM (tf32)
// ---------------------------------------------------------------------------
extern "C" void kernel_launch(void* const* d_in, const int* in_sizes, int n_in,
                              void* d_out, int out_size)
{
    const float* x      = (const float*)d_in[0];
    const float* qkv_w  = (const float*)d_in[1];
    const float* qkv_b  = (const float*)d_in[2];
    const float* qg     = (const float*)d_in[3];
    const float* qbeta  = (const float*)d_in[4];
    const float* kg     = (const float*)d_in[5];
    const float* kbeta  = (const float*)d_in[6];
    const float* proj_w = (const float*)d_in[7];
    const float* proj_b = (const float*)d_in[8];
    float* out = (float*)d_out;

    float *qkv_ptr, *heads_ptr, *attn_fb;
    cudaGetSymbolAddress((void**)&qkv_ptr, g_qkv);
    cudaGetSymbolAddress((void**)&heads_ptr, g_heads);
    cudaGetSymbolAddress((void**)&attn_fb, g_attn_fb);

    const long OUT_E  = (long)ROWS * CC;                 // 6,291,456
    const long ATTN_E = (long)BB * HH * NN * NN;         // 100,663,296
    float* attn_ptr = ((long)out_size >= OUT_E + ATTN_E) ? (out + OUT_E) : attn_fb;

    cudaFuncSetAttribute(attn_kernel, cudaFuncAttributeMaxDynamicSharedMemorySize, SMEM_ATTN);

    gemm_tf32_nt<<<dim3(QKVC / 128, ROWS / 128), 256>>>(x, qkv_w, qkv_b, qkv_ptr,
                                                        ROWS, QKVC, CC);
    ln_qk<<<(ROWS * 24) / 8, 256>>>(qkv_ptr, qg, qbeta, kg, kbeta);
    attn_kernel<<<dim3(32, BB * HH), 256, SMEM_ATTN>>>(qkv_ptr, attn_ptr, heads_ptr);
    gemm_tf32_nt<<<dim3(CC / 128, ROWS / 128), 256>>>(heads_ptr, proj_w, proj_b, out,
                                                      ROWS, CC, CC);
}

// round 7
// speedup vs baseline: 1.9638x; 1.8164x over previous
#include <cuda_runtime.h>
#include <cstdint>

// Problem constants
#define BB 8
#define NN 1024
#define CC 768
#define HH 12
#define DD 64
#define ROWS (BB * NN)          // 8192
#define QKVC (3 * CC)           // 2304

// Scratch (allocation-free rule: __device__ globals)
__device__ float g_qkv[ROWS * QKVC];                 // 75.5 MB
__device__ float g_heads[ROWS * CC];                 // 25 MB
__device__ float g_attn_fb[BB * HH * NN * NN];       // 402 MB fallback if attn not in d_out

// ---------------------------------------------------------------------------
// TF32 helpers (3xTF32 split-precision on the tensor pipe)
// ---------------------------------------------------------------------------
__device__ __forceinline__ uint32_t f2tf(float x) {
    uint32_t r;
    asm("cvt.rna.tf32.f32 %0, %1;" : "=r"(r) : "f"(x));
    return r;
}

__device__ __forceinline__ void mma8(float (&c)[4], const uint32_t (&a)[4],
                                     const uint32_t (&b)[2]) {
    asm volatile(
        "mma.sync.aligned.m16n8k8.row.col.f32.tf32.tf32.f32 "
        "{%0,%1,%2,%3},{%4,%5,%6,%7},{%8,%9},{%0,%1,%2,%3};"
        : "+f"(c[0]), "+f"(c[1]), "+f"(c[2]), "+f"(c[3])
        : "r"(a[0]), "r"(a[1]), "r"(a[2]), "r"(a[3]), "r"(b[0]), "r"(b[1]));
}

#define BKK 16
#define PAD 136   // frag LDS bank = 8*tig + gid -> conflict-free

__device__ __forceinline__ void split_store(uint32_t (*s)[BKK][PAD], int k, int r,
                                            float4 v) {
    float xs[4] = {v.x, v.y, v.z, v.w};
#pragma unroll
    for (int j = 0; j < 4; j++) {
        uint32_t hi = f2tf(xs[j]);
        s[0][k + j][r] = hi;
        s[1][k + j][r] = f2tf(xs[j] - __uint_as_float(hi));
    }
}

// ---------------------------------------------------------------------------
// TF32 tensor-core GEMM (NT): C[M,N] = A[M,K] * B[N,K]^T + bias[N]
// (validated R3/R6: rel_err ~1e-5, 279us for the QKV GEMM)
// ---------------------------------------------------------------------------
__global__ __launch_bounds__(256) void gemm_tf32_nt(
    const float* __restrict__ A, const float* __restrict__ Bm,
    const float* __restrict__ bias, float* __restrict__ C,
    int M, int N, int K)
{
    __shared__ __align__(16) uint32_t As[2][BKK][PAD];
    __shared__ __align__(16) uint32_t Bs[2][BKK][PAD];

    const int tid = threadIdx.x;
    const int m0 = blockIdx.y * 128;
    const int n0 = blockIdx.x * 128;
    const int lane = tid & 31, warp = tid >> 5;
    const int gid = lane >> 2, tig = lane & 3;
    const int wm = (warp >> 2) * 64;
    const int wn = (warp & 3) * 32;

    const int lrow = tid >> 2;
    const int lkq = (tid & 3) * 4;
    const float* Ap = A + (size_t)(m0 + lrow) * K + lkq;
    const float* Bp = Bm + (size_t)(n0 + lrow) * K + lkq;
    const size_t rstep = (size_t)64 * K;

    float c[4][4][4];
#pragma unroll
    for (int i = 0; i < 4; i++)
#pragma unroll
        for (int j = 0; j < 4; j++)
#pragma unroll
            for (int q = 0; q < 4; q++) c[i][j][q] = 0.f;

    float4 pa0 = *(const float4*)(Ap);
    float4 pa1 = *(const float4*)(Ap + rstep);
    float4 pb0 = *(const float4*)(Bp);
    float4 pb1 = *(const float4*)(Bp + rstep);

    const int nkt = K / BKK;
    for (int kt = 0; kt < nkt; kt++) {
        split_store(As, lkq, lrow, pa0);
        split_store(As, lkq, lrow + 64, pa1);
        split_store(Bs, lkq, lrow, pb0);
        split_store(Bs, lkq, lrow + 64, pb1);
        __syncthreads();

        if (kt + 1 < nkt) {
            const float* Ap2 = Ap + (size_t)(kt + 1) * BKK;
            const float* Bp2 = Bp + (size_t)(kt + 1) * BKK;
            pa0 = *(const float4*)(Ap2);
            pa1 = *(const float4*)(Ap2 + rstep);
            pb0 = *(const float4*)(Bp2);
            pb1 = *(const float4*)(Bp2 + rstep);
        }

#pragma unroll
        for (int s = 0; s < 2; s++) {
            const int k0 = s * 8 + tig, k1 = k0 + 4;
            uint32_t ah[4][4], al[4][4], bh[4][2], bl[4][2];
#pragma unroll
            for (int mi = 0; mi < 4; mi++) {
                int ra = wm + mi * 16 + gid;
                ah[mi][0] = As[0][k0][ra];     ah[mi][1] = As[0][k0][ra + 8];
                ah[mi][2] = As[0][k1][ra];     ah[mi][3] = As[0][k1][ra + 8];
                al[mi][0] = As[1][k0][ra];     al[mi][1] = As[1][k0][ra + 8];
                al[mi][2] = As[1][k1][ra];     al[mi][3] = As[1][k1][ra + 8];
            }
#pragma unroll
            for (int ni = 0; ni < 4; ni++) {
                int rb = wn + ni * 8 + gid;
                bh[ni][0] = Bs[0][k0][rb];     bh[ni][1] = Bs[0][k1][rb];
                bl[ni][0] = Bs[1][k0][rb];     bl[ni][1] = Bs[1][k1][rb];
            }
#pragma unroll
            for (int mi = 0; mi < 4; mi++)
#pragma unroll
                for (int ni = 0; ni < 4; ni++) {
                    mma8(c[mi][ni], ah[mi], bl[ni]);
                    mma8(c[mi][ni], al[mi], bh[ni]);
                    mma8(c[mi][ni], ah[mi], bh[ni]);
                }
        }
        __syncthreads();
    }

#pragma unroll
    for (int mi = 0; mi < 4; mi++) {
        int row0 = m0 + wm + mi * 16 + gid;
#pragma unroll
        for (int ni = 0; ni < 4; ni++) {
            int col = n0 + wn + ni * 8 + tig * 2;
            float2 bb = *(const float2*)&bias[col];
            float2 o0 = make_float2(c[mi][ni][0] + bb.x, c[mi][ni][1] + bb.y);
            float2 o1 = make_float2(c[mi][ni][2] + bb.x, c[mi][ni][3] + bb.y);
            *(float2*)&C[(size_t)row0 * N + col] = o0;
            *(float2*)&C[(size_t)(row0 + 8) * N + col] = o1;
        }
    }
}

// ---------------------------------------------------------------------------
// LayerNorm over head_dim=64 for q (part 0, also *SCALE) and k (part 1)
// ---------------------------------------------------------------------------
__global__ __launch_bounds__(256) void ln_qk(
    float* __restrict__ qkv,
    const float* __restrict__ qg, const float* __restrict__ qb,
    const float* __restrict__ kg, const float* __restrict__ kb)
{
    int wid = (blockIdx.x * blockDim.x + threadIdx.x) >> 5;
    int lane = threadIdx.x & 31;
    int ph = wid % 24;
    int row = wid / 24;
    int part = ph / HH;
    int h = ph % HH;

    float* p = qkv + (size_t)row * QKVC + part * CC + h * DD;
    float x0 = p[lane];
    float x1 = p[lane + 32];
    float s = x0 + x1;
    float s2 = x0 * x0 + x1 * x1;
#pragma unroll
    for (int o = 16; o; o >>= 1) {
        s += __shfl_xor_sync(0xffffffffu, s, o);
        s2 += __shfl_xor_sync(0xffffffffu, s2, o);
    }
    float mu = s * (1.f / 64.f);
    float var = s2 * (1.f / 64.f) - mu * mu;
    float inv = rsqrtf(var + 1e-5f);
    const float* g = part ? kg : qg;
    const float* be = part ? kb : qb;
    float scale = part ? 1.0f : 0.125f;   // SCALE = 64^-0.5
    p[lane]      = ((x0 - mu) * inv * g[lane]      + be[lane])      * scale;
    p[lane + 32] = ((x1 - mu) * inv * g[lane + 32] + be[lane + 32]) * scale;
}

// ---------------------------------------------------------------------------
// Scores: batched NT GEMM. S[bh][1024,1024] = Q_b,h @ K_b,h^T (raw, pre-softmax).
// Same proven tile structure; lda/ldb = QKVC, K=64, no bias. Grid (8,8,96).
// ---------------------------------------------------------------------------
__global__ __launch_bounds__(256) void scores_tf32(
    const float* __restrict__ qkv, float* __restrict__ attn)
{
    __shared__ __align__(16) uint32_t As[2][BKK][PAD];
    __shared__ __align__(16) uint32_t Bs[2][BKK][PAD];

    const int tid = threadIdx.x;
    const int m0 = blockIdx.y * 128;
    const int n0 = blockIdx.x * 128;
    const int bh = blockIdx.z;
    const int b = bh / HH, h = bh % HH;
    const float* Aq = qkv + (size_t)b * NN * QKVC + h * DD;   // Q rows, lda QKVC
    const float* Bk = Aq + CC;                                 // K rows
    float* C = attn + (size_t)bh * NN * NN;

    const int lane = tid & 31, warp = tid >> 5;
    const int gid = lane >> 2, tig = lane & 3;
    const int wm = (warp >> 2) * 64;
    const int wn = (warp & 3) * 32;

    const int lrow = tid >> 2;
    const int lkq = (tid & 3) * 4;
    const float* Ap = Aq + (size_t)(m0 + lrow) * QKVC + lkq;
    const float* Bp = Bk + (size_t)(n0 + lrow) * QKVC + lkq;
    const size_t rstep = (size_t)64 * QKVC;

    float c[4][4][4];
#pragma unroll
    for (int i = 0; i < 4; i++)
#pragma unroll
        for (int j = 0; j < 4; j++)
#pragma unroll
            for (int q = 0; q < 4; q++) c[i][j][q] = 0.f;

    float4 pa0 = *(const float4*)(Ap);
    float4 pa1 = *(const float4*)(Ap + rstep);
    float4 pb0 = *(const float4*)(Bp);
    float4 pb1 = *(const float4*)(Bp + rstep);

    for (int kt = 0; kt < 4; kt++) {      // K = 64 = 4 * BKK
        split_store(As, lkq, lrow, pa0);
        split_store(As, lkq, lrow + 64, pa1);
        split_store(Bs, lkq, lrow, pb0);
        split_store(Bs, lkq, lrow + 64, pb1);
        __syncthreads();

        if (kt + 1 < 4) {
            const float* Ap2 = Ap + (kt + 1) * BKK;
            const float* Bp2 = Bp + (kt + 1) * BKK;
            pa0 = *(const float4*)(Ap2);
            pa1 = *(const float4*)(Ap2 + rstep);
            pb0 = *(const float4*)(Bp2);
            pb1 = *(const float4*)(Bp2 + rstep);
        }

#pragma unroll
        for (int s = 0; s < 2; s++) {
            const int k0 = s * 8 + tig, k1 = k0 + 4;
            uint32_t ah[4][4], al[4][4], bh2[4][2], bl2[4][2];
#pragma unroll
            for (int mi = 0; mi < 4; mi++) {
                int ra = wm + mi * 16 + gid;
                ah[mi][0] = As[0][k0][ra];     ah[mi][1] = As[0][k0][ra + 8];
                ah[mi][2] = As[0][k1][ra];     ah[mi][3] = As[0][k1][ra + 8];
                al[mi][0] = As[1][k0][ra];     al[mi][1] = As[1][k0][ra + 8];
                al[mi][2] = As[1][k1][ra];     al[mi][3] = As[1][k1][ra + 8];
            }
#pragma unroll
            for (int ni = 0; ni < 4; ni++) {
                int rb = wn + ni * 8 + gid;
                bh2[ni][0] = Bs[0][k0][rb];    bh2[ni][1] = Bs[0][k1][rb];
                bl2[ni][0] = Bs[1][k0][rb];    bl2[ni][1] = Bs[1][k1][rb];
            }
#pragma unroll
            for (int mi = 0; mi < 4; mi++)
#pragma unroll
                for (int ni = 0; ni < 4; ni++) {
                    mma8(c[mi][ni], ah[mi], bl2[ni]);
                    mma8(c[mi][ni], al[mi], bh2[ni]);
                    mma8(c[mi][ni], ah[mi], bh2[ni]);
                }
        }
        __syncthreads();
    }

#pragma unroll
    for (int mi = 0; mi < 4; mi++) {
        int row0 = m0 + wm + mi * 16 + gid;
#pragma unroll
        for (int ni = 0; ni < 4; ni++) {
            int col = n0 + wn + ni * 8 + tig * 2;
            *(float2*)&C[(size_t)row0 * NN + col]       = make_float2(c[mi][ni][0], c[mi][ni][1]);
            *(float2*)&C[(size_t)(row0 + 8) * NN + col] = make_float2(c[mi][ni][2], c[mi][ni][3]);
        }
    }
}

// ---------------------------------------------------------------------------
// Row softmax in place: one warp per row, row held in registers.
// Grid: 96*1024/8 = 12288 blocks of 256 threads (8 rows/block).
// ---------------------------------------------------------------------------
__global__ __launch_bounds__(256) void softmax_rows(float* __restrict__ attn)
{
    const int warp = threadIdx.x >> 5, lane = threadIdx.x & 31;
    const size_t row = (size_t)blockIdx.x * 8 + warp;
    float* p = attn + row * NN;

    float4 v[8];
    float m = -1e30f;
#pragma unroll
    for (int it = 0; it < 8; it++) {
        v[it] = *(const float4*)&p[it * 128 + lane * 4];
        m = fmaxf(m, fmaxf(fmaxf(v[it].x, v[it].y), fmaxf(v[it].z, v[it].w)));
    }
#pragma unroll
    for (int o = 16; o; o >>= 1) m = fmaxf(m, __shfl_xor_sync(0xffffffffu, m, o));
    float sum = 0.f;
#pragma unroll
    for (int it = 0; it < 8; it++) {
        v[it].x = __expf(v[it].x - m); v[it].y = __expf(v[it].y - m);
        v[it].z = __expf(v[it].z - m); v[it].w = __expf(v[it].w - m);
        sum += v[it].x + v[it].y + v[it].z + v[it].w;
    }
#pragma unroll
    for (int o = 16; o; o >>= 1) sum += __shfl_xor_sync(0xffffffffu, sum, o);
    float inv = 1.f / sum;
#pragma unroll
    for (int it = 0; it < 8; it++) {
        v[it].x *= inv; v[it].y *= inv; v[it].z *= inv; v[it].w *= inv;
        *(float4*)&p[it * 128 + lane * 4] = v[it];
    }
}

// ---------------------------------------------------------------------------
// PV: batched NN GEMM. heads = P @ V.  A = attn[bh] (fp32, lda NN),
// B = V rows (ldb QKVC, d contiguous). Block tile 128m x 64n, BK=16, 64 iters.
// Grid (8, 96). 8 warps as 4(m) x 2(n) -> 32x32 warp tiles.
// ---------------------------------------------------------------------------
#define PVB 72    // 72%32=8 -> b-frag bank 8*tig+gid conflict-free

__global__ __launch_bounds__(256) void pv_tf32(
    const float* __restrict__ attn, const float* __restrict__ qkv,
    float* __restrict__ heads)
{
    __shared__ __align__(16) uint32_t As[2][BKK][PAD];
    __shared__ __align__(16) uint32_t Bs[2][BKK][PVB];

    const int tid = threadIdx.x;
    const int m0 = blockIdx.x * 128;
    const int bh = blockIdx.y;
    const int b = bh / HH, h = bh % HH;
    const float* A = attn + (size_t)bh * NN * NN;
    const float* V = qkv + (size_t)b * NN * QKVC + 2 * CC + h * DD;

    const int lane = tid & 31, warp = tid >> 5;
    const int gid = lane >> 2, tig = lane & 3;
    const int wm = (warp >> 1) * 32;
    const int wn = (warp & 1) * 32;

    // A loader: 128 rows x 16 k; each thread: row tid>>1, k (tid&1)*8 (2 float4)
    const int alr = tid >> 1, alk = (tid & 1) * 8;
    // B loader: 16 k-rows x 64 n; each thread one float4: k tid>>4, n (tid&15)*4
    const int blr = tid >> 4, bnq = (tid & 15) * 4;

    const float* Apt = A + (size_t)(m0 + alr) * NN + alk;
    const float* Bpt = V + (size_t)blr * QKVC + bnq;

    float c[2][4][4];
#pragma unroll
    for (int i = 0; i < 2; i++)
#pragma unroll
        for (int j = 0; j < 4; j++)
#pragma unroll
            for (int q = 0; q < 4; q++) c[i][j][q] = 0.f;

    float4 pa0 = *(const float4*)(Apt);
    float4 pa1 = *(const float4*)(Apt + 4);
    float4 pb0 = *(const float4*)(Bpt);

    for (int kt = 0; kt < 64; kt++) {
        split_store(As, alk, alr, pa0);
        split_store(As, alk + 4, alr, pa1);
        {
            float xs[4] = {pb0.x, pb0.y, pb0.z, pb0.w};
#pragma unroll
            for (int j = 0; j < 4; j++) {
                uint32_t hi = f2tf(xs[j]);
                Bs[0][blr][bnq + j] = hi;
                Bs[1][blr][bnq + j] = f2tf(xs[j] - __uint_as_float(hi));
            }
        }
        __syncthreads();

        if (kt + 1 < 64) {
            const float* Ap2 = Apt + (kt + 1) * BKK;
            const float* Bp2 = Bpt + (size_t)(kt + 1) * BKK * QKVC;
            pa0 = *(const float4*)(Ap2);
            pa1 = *(const float4*)(Ap2 + 4);
            pb0 = *(const float4*)(Bp2);
        }

#pragma unroll
        for (int s = 0; s < 2; s++) {
            const int k0 = s * 8 + tig, k1 = k0 + 4;
            uint32_t ah[2][4], al[2][4], bh2[4][2], bl2[4][2];
#pragma unroll
            for (int mi = 0; mi < 2; mi++) {
                int ra = wm + mi * 16 + gid;
                ah[mi][0] = As[0][k0][ra];     ah[mi][1] = As[0][k0][ra + 8];
                ah[mi][2] = As[0][k1][ra];     ah[mi][3] = As[0][k1][ra + 8];
                al[mi][0] = As[1][k0][ra];     al[mi][1] = As[1][k0][ra + 8];
                al[mi][2] = As[1][k1][ra];     al[mi][3] = As[1][k1][ra + 8];
            }
#pragma unroll
            for (int ni = 0; ni < 4; ni++) {
                int rb = wn + ni * 8 + gid;
                bh2[ni][0] = Bs[0][k0][rb];    bh2[ni][1] = Bs[0][k1][rb];
                bl2[ni][0] = Bs[1][k0][rb];    bl2[ni][1] = Bs[1][k1][rb];
            }
#pragma unroll
            for (int mi = 0; mi < 2; mi++)
#pragma unroll
                for (int ni = 0; ni < 4; ni++) {
                    mma8(c[mi][ni], ah[mi], bl2[ni]);
                    mma8(c[mi][ni], al[mi], bh2[ni]);
                    mma8(c[mi][ni], ah[mi], bh2[ni]);
                }
        }
        __syncthreads();
    }

    // heads[(b*NN + row)*CC + h*DD + col]
#pragma unroll
    for (int mi = 0; mi < 2; mi++) {
        int row0 = m0 + wm + mi * 16 + gid;
#pragma unroll
        for (int ni = 0; ni < 4; ni++) {
            int col = wn + ni * 8 + tig * 2;
            *(float2*)&heads[((size_t)b * NN + row0) * CC + h * DD + col] =
                make_float2(c[mi][ni][0], c[mi][ni][1]);
            *(float2*)&heads[((size_t)b * NN + row0 + 8) * CC + h * DD + col] =
                make_float2(c[mi][ni][2], c[mi][ni][3]);
        }
    }
}

// ---------------------------------------------------------------------------
// Launch: qkv GEMM -> LN -> scores GEMM -> softmax -> PV GEMM -> proj GEMM
// ---------------------------------------------------------------------------
extern "C" void kernel_launch(void* const* d_in, const int* in_sizes, int n_in,
                              void* d_out, int out_size)
{
    const float* x      = (const float*)d_in[0];
    const float* qkv_w  = (const float*)d_in[1];
    const float* qkv_b  = (const float*)d_in[2];
    const float* qg     = (const float*)d_in[3];
    const float* qbeta  = (const float*)d_in[4];
    const float* kg     = (const float*)d_in[5];
    const float* kbeta  = (const float*)d_in[6];
    const float* proj_w = (const float*)d_in[7];
    const float* proj_b = (const float*)d_in[8];
    float* out = (float*)d_out;

    float *qkv_ptr, *heads_ptr, *attn_fb;
    cudaGetSymbolAddress((void**)&qkv_ptr, g_qkv);
    cudaGetSymbolAddress((void**)&heads_ptr, g_heads);
    cudaGetSymbolAddress((void**)&attn_fb, g_attn_fb);

    const long OUT_E  = (long)ROWS * CC;                 // 6,291,456
    const long ATTN_E = (long)BB * HH * NN * NN;         // 100,663,296
    float* attn_ptr = ((long)out_size >= OUT_E + ATTN_E) ? (out + OUT_E) : attn_fb;

    // 1. qkv = x @ qkv_w^T + qkv_b
    gemm_tf32_nt<<<dim3(QKVC / 128, ROWS / 128), 256>>>(x, qkv_w, qkv_b, qkv_ptr,
                                                        ROWS, QKVC, CC);
    // 2. LayerNorm q (with *SCALE) and k, in place
    ln_qk<<<(ROWS * 24) / 8, 256>>>(qkv_ptr, qg, qbeta, kg, kbeta);
    // 3. raw scores into attn buffer
    scores_tf32<<<dim3(8, 8, BB * HH), 256>>>(qkv_ptr, attn_ptr);
    // 4. softmax in place (produces final attn output)
    softmax_rows<<<BB * HH * NN / 8, 256>>>(attn_ptr);
    // 5. heads = attn @ V
    pv_tf32<<<dim3(8, BB * HH), 256>>>(attn_ptr, qkv_ptr, heads_ptr);
    // 6. out = heads @ proj_w^T + proj_b
    gemm_tf32_nt<<<dim3(CC / 128, ROWS / 128), 256>>>(heads_ptr, proj_w, proj_b, out,
                                                      ROWS, CC, CC);
}